// round 5
// baseline (speedup 1.0000x reference)
#include <cuda_runtime.h>
#include <cuda_bf16.h>

// NonLocalAttention: B=8, C=256, Ci=128, H=W=64, N=4096, M=1024
#define BB 8
#define CC 256
#define CI 128
#define WW 64
#define NN 4096
#define MM 1024

// fp32 intermediates
__device__ float g_phif[(size_t)BB * NN * CI];
__device__ float g_gf  [(size_t)BB * NN * CI];
__device__ float g_y   [(size_t)BB * NN * CI];
// pre-split bf16 hi/lo packed intermediates
__device__ unsigned g_qH  [(size_t)BB * NN * 64];   // Q  [b][n][kpair]
__device__ unsigned g_qL  [(size_t)BB * NN * 64];
__device__ unsigned g_kH  [(size_t)BB * MM * 64];   // K  [b][m][kpair]
__device__ unsigned g_kL  [(size_t)BB * MM * 64];
__device__ unsigned g_vTH [(size_t)BB * CI * (MM/2)]; // V^T [b][ci][mpair]
__device__ unsigned g_vTL [(size_t)BB * CI * (MM/2)];

// ---------------------------------------------------------------------------
// helpers
// ---------------------------------------------------------------------------
__device__ __forceinline__ void pack2(unsigned& H, unsigned& L, float x0, float x1) {
    float h0 = __bfloat162float(__float2bfloat16_rn(x0));
    float h1 = __bfloat162float(__float2bfloat16_rn(x1));
    __nv_bfloat162 hh = __floats2bfloat162_rn(h0, h1);
    __nv_bfloat162 ll = __floats2bfloat162_rn(x0 - h0, x1 - h1);
    H = *(unsigned*)&hh;
    L = *(unsigned*)&ll;
}
__device__ __forceinline__ void mma16(float* c, unsigned a0, unsigned a1,
                                      unsigned a2, unsigned a3,
                                      unsigned b0, unsigned b1) {
    asm volatile(
        "mma.sync.aligned.m16n8k16.row.col.f32.bf16.bf16.f32 "
        "{%0,%1,%2,%3},{%4,%5,%6,%7},{%8,%9},{%0,%1,%2,%3};\n"
        : "+f"(c[0]), "+f"(c[1]), "+f"(c[2]), "+f"(c[3])
        : "r"(a0), "r"(a1), "r"(a2), "r"(a3), "r"(b0), "r"(b1));
}
__device__ __forceinline__ void ldsm4(unsigned& d0, unsigned& d1,
                                      unsigned& d2, unsigned& d3, const unsigned* p) {
    unsigned a = (unsigned)__cvta_generic_to_shared((void*)p);
    asm volatile("ldmatrix.sync.aligned.m8n8.x4.shared.b16 {%0,%1,%2,%3}, [%4];"
        : "=r"(d0), "=r"(d1), "=r"(d2), "=r"(d3) : "r"(a));
}

// ---------------------------------------------------------------------------
// Kernel 1: 3-way 1x1 conv, bf16x3 + ldmatrix.
// grid (N/64, 6, B); yy/2 selects proj, yy&1 selects ci half. Block 64n x 64j.
// theta output goes pre-packed to g_qH/g_qL; phi/g stay fp32.
// ---------------------------------------------------------------------------
__global__ __launch_bounds__(256) void proj3_tc(
    const float* __restrict__ x,
    const float* __restrict__ w_t, const float* __restrict__ b_t,
    const float* __restrict__ w_p, const float* __restrict__ b_p,
    const float* __restrict__ w_g, const float* __restrict__ b_g)
{
    __shared__ unsigned Xh[64 * 20], Xl[64 * 20];   // x  [n][kpair] pitch 20
    __shared__ unsigned Wh[64 * 20], Wl[64 * 20];   // w  [j][kpair]

    const int b  = blockIdx.z;
    const int n0 = blockIdx.x * 64;
    const int yy = blockIdx.y;

    const float* w;  const float* bias;  float* dstf = 0;  bool is_theta = false;
    if (yy < 2)      { w = w_t; bias = b_t; is_theta = true; }
    else if (yy < 4) { w = w_p; bias = b_p; dstf = g_phif; }
    else             { w = w_g; bias = b_g; dstf = g_gf;  }
    const int cib = (yy & 1) * 64;

    const int tid  = threadIdx.x;
    const int lane = tid & 31, warp = tid >> 5;
    const int gid  = lane >> 2, t4 = lane & 3;
    const int mw   = (warp >> 1) * 16, nw = (warp & 1) * 32;
    const int l16  = lane & 15, lh = lane >> 4;

    float acc[4][4] = {};
    const float* xb = x + (size_t)b * CC * NN;
    const int xn  = tid & 63;
    const int kp0 = tid >> 6;

    for (int c0 = 0; c0 < CC; c0 += 32) {
        __syncthreads();
        #pragma unroll
        for (int i = 0; i < 4; i++) {
            int kp = kp0 + i * 4;
            float v0 = xb[(size_t)(c0 + 2 * kp) * NN + n0 + xn];
            float v1 = xb[(size_t)(c0 + 2 * kp + 1) * NN + n0 + xn];
            unsigned H, L; pack2(H, L, v0, v1);
            Xh[xn * 20 + kp] = H;
            Xl[xn * 20 + kp] = L;
        }
        #pragma unroll
        for (int it = 0; it < 2; it++) {
            int j = tid + it * 256;
            int r = j >> 3, kq = j & 7;
            float4 v = *(const float4*)&w[(size_t)(cib + r) * CC + c0 + kq * 4];
            unsigned h0, l0, h1, l1;
            pack2(h0, l0, v.x, v.y);
            pack2(h1, l1, v.z, v.w);
            *(uint2*)&Wh[r * 20 + kq * 2] = make_uint2(h0, h1);
            *(uint2*)&Wl[r * 20 + kq * 2] = make_uint2(l0, l1);
        }
        __syncthreads();

        #pragma unroll
        for (int st = 0; st < 2; st++) {
            unsigned ah0, ah1, ah2, ah3, al0, al1, al2, al3;
            ldsm4(ah0, ah1, ah2, ah3, &Xh[(mw + l16) * 20 + st * 8 + lh * 4]);
            ldsm4(al0, al1, al2, al3, &Xl[(mw + l16) * 20 + st * 8 + lh * 4]);
            #pragma unroll
            for (int ntp = 0; ntp < 2; ntp++) {
                unsigned bh0, bh1, bh2, bh3, bl0, bl1, bl2, bl3;
                ldsm4(bh0, bh1, bh2, bh3, &Wh[(nw + ntp * 16 + l16) * 20 + st * 8 + lh * 4]);
                ldsm4(bl0, bl1, bl2, bl3, &Wl[(nw + ntp * 16 + l16) * 20 + st * 8 + lh * 4]);
                mma16(acc[2*ntp],   ah0, ah1, ah2, ah3, bh0, bh2);
                mma16(acc[2*ntp],   ah0, ah1, ah2, ah3, bl0, bl2);
                mma16(acc[2*ntp],   al0, al1, al2, al3, bh0, bh2);
                mma16(acc[2*ntp+1], ah0, ah1, ah2, ah3, bh1, bh3);
                mma16(acc[2*ntp+1], ah0, ah1, ah2, ah3, bl1, bl3);
                mma16(acc[2*ntp+1], al0, al1, al2, al3, bh1, bh3);
            }
        }
    }

    const size_t base = (size_t)b * NN + n0;
    #pragma unroll
    for (int nt = 0; nt < 4; nt++) {
        int col = cib + nw + nt * 8 + 2 * t4;
        float bb0 = bias[col], bb1 = bias[col + 1];
        int r0 = mw + gid;
        float2 v0 = {acc[nt][0] + bb0, acc[nt][1] + bb1};
        float2 v1 = {acc[nt][2] + bb0, acc[nt][3] + bb1};
        if (is_theta) {
            int kw = col >> 1;
            unsigned H, L;
            pack2(H, L, v0.x, v0.y);
            g_qH[(base + r0) * 64 + kw] = H;
            g_qL[(base + r0) * 64 + kw] = L;
            pack2(H, L, v1.x, v1.y);
            g_qH[(base + r0 + 8) * 64 + kw] = H;
            g_qL[(base + r0 + 8) * 64 + kw] = L;
        } else {
            *(float2*)&dstf[(base + r0) * CI + col]     = v0;
            *(float2*)&dstf[(base + r0 + 8) * CI + col] = v1;
        }
    }
}

// ---------------------------------------------------------------------------
// Kernel 2a: pool phi -> packed bf16 hi/lo [b][m][kpair]
// ---------------------------------------------------------------------------
__global__ __launch_bounds__(256) void pool_phi_kernel()
{
    int idx = blockIdx.x * 256 + threadIdx.x;     // BB*MM*32
    int c4 = (idx & 31) * 4;
    int m  = (idx >> 5) & (MM - 1);
    int b  = idx >> 15;
    int hp = m >> 5, wp = m & 31;
    int n00 = (hp * 2) * WW + wp * 2;
    size_t base = ((size_t)b * NN + n00) * CI + c4;

    float4 a0 = *(const float4*)&g_phif[base];
    float4 a1 = *(const float4*)&g_phif[base + CI];
    float4 a2 = *(const float4*)&g_phif[base + (size_t)WW * CI];
    float4 a3 = *(const float4*)&g_phif[base + (size_t)WW * CI + CI];
    float4 r;
    r.x = fmaxf(fmaxf(a0.x, a1.x), fmaxf(a2.x, a3.x));
    r.y = fmaxf(fmaxf(a0.y, a1.y), fmaxf(a2.y, a3.y));
    r.z = fmaxf(fmaxf(a0.z, a1.z), fmaxf(a2.z, a3.z));
    r.w = fmaxf(fmaxf(a0.w, a1.w), fmaxf(a2.w, a3.w));

    unsigned h0, l0, h1, l1;
    pack2(h0, l0, r.x, r.y);
    pack2(h1, l1, r.z, r.w);
    size_t dst = ((size_t)b * MM + m) * 64 + (c4 >> 1);
    *(uint2*)&g_kH[dst] = make_uint2(h0, h1);
    *(uint2*)&g_kL[dst] = make_uint2(l0, l1);
}

// ---------------------------------------------------------------------------
// Kernel 2b: pool g + transpose -> V^T packed along m-pairs [b][ci][mpair]
// ---------------------------------------------------------------------------
__global__ __launch_bounds__(256) void pool_vT_kernel()
{
    int idx = blockIdx.x * 256 + threadIdx.x;     // BB * 512 * 128
    int ci = idx & 127;
    int mp = (idx >> 7) & 511;
    int b  = idx >> 16;

    float v[2];
    #pragma unroll
    for (int j = 0; j < 2; j++) {
        int m = 2 * mp + j;
        int hp = m >> 5, wp = m & 31;
        int n00 = (hp * 2) * WW + wp * 2;
        size_t base = ((size_t)b * NN + n00) * CI + ci;
        float a0 = g_gf[base];
        float a1 = g_gf[base + CI];
        float a2 = g_gf[base + (size_t)WW * CI];
        float a3 = g_gf[base + (size_t)WW * CI + CI];
        v[j] = fmaxf(fmaxf(a0, a1), fmaxf(a2, a3));
    }
    unsigned H, L; pack2(H, L, v[0], v[1]);
    size_t dst = ((size_t)b * CI + ci) * (MM / 2) + mp;
    g_vTH[dst] = H;
    g_vTL[dst] = L;
}

// ---------------------------------------------------------------------------
// Kernel 3: flash attention. QK bf16x3, PV bf16x3, all fragments via ldmatrix,
// P kept in registers (S C-fragment == PV A-fragment layout).
// Block 128 q, 8 warps x 16 q, m tiles of 64.
// ---------------------------------------------------------------------------
#define ATTN_WORDS (2*128*68 + 2*64*68 + 2*128*36)
#define ATTN_SMEM_BYTES (ATTN_WORDS * 4)

__global__ __launch_bounds__(256, 1) void attn_tc()
{
    extern __shared__ unsigned smu[];
    unsigned* QhW = smu;                 // [q=128][kw] pitch 68
    unsigned* QlW = QhW + 128 * 68;
    unsigned* KhW = QlW + 128 * 68;      // [m=64][kw] pitch 68
    unsigned* KlW = KhW + 64 * 68;
    unsigned* VtH = KlW + 64 * 68;       // [ci=128][mp] pitch 36
    unsigned* VtL = VtH + 128 * 36;

    const int b  = blockIdx.y;
    const int n0 = blockIdx.x * 128;
    const int tid  = threadIdx.x;
    const int lane = tid & 31, warp = tid >> 5;
    const int gid  = lane >> 2, t4 = lane & 3;
    const int qw   = warp * 16;
    const int l16  = lane & 15, lh = lane >> 4;

    // stage Q: straight packed copies
    const unsigned* QgH = g_qH + ((size_t)b * NN + n0) * 64;
    const unsigned* QgL = g_qL + ((size_t)b * NN + n0) * 64;
    #pragma unroll
    for (int it = 0; it < 8; it++) {
        int j = tid + it * 256;           // 128 q * 16 segs
        int q = j >> 4, sg = (j & 15) * 4;
        *(uint4*)&QhW[q * 68 + sg] = *(const uint4*)&QgH[q * 64 + sg];
        *(uint4*)&QlW[q * 68 + sg] = *(const uint4*)&QgL[q * 64 + sg];
    }

    float o[16][4];
    #pragma unroll
    for (int i = 0; i < 16; i++)
        #pragma unroll
        for (int jj = 0; jj < 4; jj++) o[i][jj] = 0.f;
    float m_lo = -1e30f, m_hi = -1e30f, l_lo = 0.f, l_hi = 0.f;

    for (int m0 = 0; m0 < MM; m0 += 64) {
        __syncthreads();
        const unsigned* KgH = g_kH + ((size_t)b * MM + m0) * 64;
        const unsigned* KgL = g_kL + ((size_t)b * MM + m0) * 64;
        const unsigned* VgH = g_vTH + (size_t)b * CI * (MM/2) + (m0 >> 1);
        const unsigned* VgL = g_vTL + (size_t)b * CI * (MM/2) + (m0 >> 1);
        #pragma unroll
        for (int it = 0; it < 4; it++) {
            int j = tid + it * 256;       // 64 m * 16 segs
            int m = j >> 4, sg = (j & 15) * 4;
            *(uint4*)&KhW[m * 68 + sg] = *(const uint4*)&KgH[m * 64 + sg];
            *(uint4*)&KlW[m * 68 + sg] = *(const uint4*)&KgL[m * 64 + sg];
            int ci = j >> 3, sv = (j & 7) * 4;   // 128 ci * 8 segs
            *(uint4*)&VtH[ci * 36 + sv] = *(const uint4*)&VgH[(size_t)ci * (MM/2) + sv];
            *(uint4*)&VtL[ci * 36 + sv] = *(const uint4*)&VgL[(size_t)ci * (MM/2) + sv];
        }
        __syncthreads();

        // S = Q K^T : bf16x3 via ldmatrix
        float s[8][4];
        #pragma unroll
        for (int nt = 0; nt < 8; nt++)
            #pragma unroll
            for (int jj = 0; jj < 4; jj++) s[nt][jj] = 0.f;

        #pragma unroll
        for (int ks = 0; ks < 8; ks++) {
            unsigned ah0, ah1, ah2, ah3, al0, al1, al2, al3;
            ldsm4(ah0, ah1, ah2, ah3, &QhW[(qw + l16) * 68 + ks * 8 + lh * 4]);
            ldsm4(al0, al1, al2, al3, &QlW[(qw + l16) * 68 + ks * 8 + lh * 4]);
            #pragma unroll
            for (int ntp = 0; ntp < 4; ntp++) {
                unsigned bh0, bh1, bh2, bh3, bl0, bl1, bl2, bl3;
                ldsm4(bh0, bh1, bh2, bh3, &KhW[(ntp * 16 + l16) * 68 + ks * 8 + lh * 4]);
                ldsm4(bl0, bl1, bl2, bl3, &KlW[(ntp * 16 + l16) * 68 + ks * 8 + lh * 4]);
                mma16(s[2*ntp],   ah0, ah1, ah2, ah3, bh0, bh2);
                mma16(s[2*ntp],   ah0, ah1, ah2, ah3, bl0, bl2);
                mma16(s[2*ntp],   al0, al1, al2, al3, bh0, bh2);
                mma16(s[2*ntp+1], ah0, ah1, ah2, ah3, bh1, bh3);
                mma16(s[2*ntp+1], ah0, ah1, ah2, ah3, bl1, bl3);
                mma16(s[2*ntp+1], al0, al1, al2, al3, bh1, bh3);
            }
        }

        // online softmax; p stays in registers (s overwritten with p)
        float mx0 = -1e30f, mx1 = -1e30f;
        #pragma unroll
        for (int nt = 0; nt < 8; nt++) {
            mx0 = fmaxf(mx0, fmaxf(s[nt][0], s[nt][1]));
            mx1 = fmaxf(mx1, fmaxf(s[nt][2], s[nt][3]));
        }
        mx0 = fmaxf(mx0, __shfl_xor_sync(0xffffffffu, mx0, 1));
        mx0 = fmaxf(mx0, __shfl_xor_sync(0xffffffffu, mx0, 2));
        mx1 = fmaxf(mx1, __shfl_xor_sync(0xffffffffu, mx1, 1));
        mx1 = fmaxf(mx1, __shfl_xor_sync(0xffffffffu, mx1, 2));
        float mn0 = fmaxf(m_lo, mx0), mn1 = fmaxf(m_hi, mx1);
        float al0 = __expf(m_lo - mn0), al1 = __expf(m_hi - mn1);
        float s0 = 0.f, s1 = 0.f;
        #pragma unroll
        for (int nt = 0; nt < 8; nt++) {
            s[nt][0] = __expf(s[nt][0] - mn0);
            s[nt][1] = __expf(s[nt][1] - mn0);
            s[nt][2] = __expf(s[nt][2] - mn1);
            s[nt][3] = __expf(s[nt][3] - mn1);
            s0 += s[nt][0] + s[nt][1];
            s1 += s[nt][2] + s[nt][3];
        }
        s0 += __shfl_xor_sync(0xffffffffu, s0, 1);
        s0 += __shfl_xor_sync(0xffffffffu, s0, 2);
        s1 += __shfl_xor_sync(0xffffffffu, s1, 1);
        s1 += __shfl_xor_sync(0xffffffffu, s1, 2);
        l_lo = l_lo * al0 + s0; m_lo = mn0;
        l_hi = l_hi * al1 + s1; m_hi = mn1;
        #pragma unroll
        for (int nt = 0; nt < 16; nt++) {
            o[nt][0] *= al0; o[nt][1] *= al0;
            o[nt][2] *= al1; o[nt][3] *= al1;
        }

        // O += P V  (bf16x3; P packed from registers, V^T fragments via ldmatrix)
        #pragma unroll
        for (int ks2 = 0; ks2 < 4; ks2++) {
            unsigned paH[4], paL[4];
            pack2(paH[0], paL[0], s[2*ks2][0],   s[2*ks2][1]);
            pack2(paH[1], paL[1], s[2*ks2][2],   s[2*ks2][3]);
            pack2(paH[2], paL[2], s[2*ks2+1][0], s[2*ks2+1][1]);
            pack2(paH[3], paL[3], s[2*ks2+1][2], s[2*ks2+1][3]);
            #pragma unroll
            for (int ntp = 0; ntp < 8; ntp++) {
                unsigned vh0, vh1, vh2, vh3, vl0, vl1, vl2, vl3;
                ldsm4(vh0, vh1, vh2, vh3, &VtH[(ntp * 16 + l16) * 36 + ks2 * 8 + lh * 4]);
                ldsm4(vl0, vl1, vl2, vl3, &VtL[(ntp * 16 + l16) * 36 + ks2 * 8 + lh * 4]);
                mma16(o[2*ntp],   paH[0], paH[1], paH[2], paH[3], vh0, vh2);
                mma16(o[2*ntp],   paH[0], paH[1], paH[2], paH[3], vl0, vl2);
                mma16(o[2*ntp],   paL[0], paL[1], paL[2], paL[3], vh0, vh2);
                mma16(o[2*ntp+1], paH[0], paH[1], paH[2], paH[3], vh1, vh3);
                mma16(o[2*ntp+1], paH[0], paH[1], paH[2], paH[3], vl1, vl3);
                mma16(o[2*ntp+1], paL[0], paL[1], paL[2], paL[3], vh1, vh3);
            }
        }
    }

    float i0 = 1.f / l_lo, i1 = 1.f / l_hi;
    float* yb = g_y + ((size_t)b * NN + n0) * CI;
    #pragma unroll
    for (int nt = 0; nt < 16; nt++) {
        int cc = nt * 8 + 2 * t4;
        float2 w0 = {o[nt][0] * i0, o[nt][1] * i0};
        float2 w1 = {o[nt][2] * i1, o[nt][3] * i1};
        *(float2*)&yb[(size_t)(qw + gid) * CI + cc]     = w0;
        *(float2*)&yb[(size_t)(qw + gid + 8) * CI + cc] = w1;
    }
}

// ---------------------------------------------------------------------------
// Kernel 4: out conv + bias + residual, bf16x3 + ldmatrix.
// ---------------------------------------------------------------------------
__global__ __launch_bounds__(256) void out_tc(
    const float* __restrict__ x,
    const float* __restrict__ wo, const float* __restrict__ bo,
    float* __restrict__ out)
{
    __shared__ unsigned Ah[64 * 20], Al[64 * 20];   // wo [c][kpair]
    __shared__ unsigned Bh[64 * 20], Bl[64 * 20];   // y  [n][kpair]

    const int b  = blockIdx.z;
    const int c0 = blockIdx.y * 64;
    const int n0 = blockIdx.x * 64;
    const int tid  = threadIdx.x;
    const int lane = tid & 31, warp = tid >> 5;
    const int gid  = lane >> 2, t4 = lane & 3;
    const int mw   = (warp >> 1) * 16, nw = (warp & 1) * 32;
    const int l16  = lane & 15, lh = lane >> 4;

    const float* yb = g_y + ((size_t)b * NN + n0) * CI;
    float acc[4][4] = {};

    for (int k0 = 0; k0 < CI; k0 += 32) {
        __syncthreads();
        #pragma unroll
        for (int it = 0; it < 2; it++) {
            int j = tid + it * 256;
            int r = j >> 3, kq = j & 7;
            float4 a = *(const float4*)&wo[(size_t)(c0 + r) * CI + k0 + kq * 4];
            unsigned h0, l0, h1, l1;
            pack2(h0, l0, a.x, a.y);
            pack2(h1, l1, a.z, a.w);
            *(uint2*)&Ah[r * 20 + kq * 2] = make_uint2(h0, h1);
            *(uint2*)&Al[r * 20 + kq * 2] = make_uint2(l0, l1);
            float4 yv = *(const float4*)&yb[(size_t)r * CI + k0 + kq * 4];
            pack2(h0, l0, yv.x, yv.y);
            pack2(h1, l1, yv.z, yv.w);
            *(uint2*)&Bh[r * 20 + kq * 2] = make_uint2(h0, h1);
            *(uint2*)&Bl[r * 20 + kq * 2] = make_uint2(l0, l1);
        }
        __syncthreads();

        #pragma unroll
        for (int st = 0; st < 2; st++) {
            unsigned ah0, ah1, ah2, ah3, al0, al1, al2, al3;
            ldsm4(ah0, ah1, ah2, ah3, &Ah[(mw + l16) * 20 + st * 8 + lh * 4]);
            ldsm4(al0, al1, al2, al3, &Al[(mw + l16) * 20 + st * 8 + lh * 4]);
            #pragma unroll
            for (int ntp = 0; ntp < 2; ntp++) {
                unsigned bh0, bh1, bh2, bh3, bl0, bl1, bl2, bl3;
                ldsm4(bh0, bh1, bh2, bh3, &Bh[(nw + ntp * 16 + l16) * 20 + st * 8 + lh * 4]);
                ldsm4(bl0, bl1, bl2, bl3, &Bl[(nw + ntp * 16 + l16) * 20 + st * 8 + lh * 4]);
                mma16(acc[2*ntp],   ah0, ah1, ah2, ah3, bh0, bh2);
                mma16(acc[2*ntp],   ah0, ah1, ah2, ah3, bl0, bl2);
                mma16(acc[2*ntp],   al0, al1, al2, al3, bh0, bh2);
                mma16(acc[2*ntp+1], ah0, ah1, ah2, ah3, bh1, bh3);
                mma16(acc[2*ntp+1], ah0, ah1, ah2, ah3, bl1, bl3);
                mma16(acc[2*ntp+1], al0, al1, al2, al3, bh1, bh3);
            }
        }
    }

    #pragma unroll
    for (int nt = 0; nt < 4; nt++) {
        int c = c0 + mw + gid;
        int n = n0 + nw + nt * 8 + 2 * t4;
        float bias0 = bo[c], bias1 = bo[c + 8];
        size_t off0 = ((size_t)b * CC + c) * NN + n;
        size_t off1 = ((size_t)b * CC + c + 8) * NN + n;
        float2 x0 = *(const float2*)&x[off0];
        float2 x1 = *(const float2*)&x[off1];
        float2 r0 = {acc[nt][0] + x0.x + bias0, acc[nt][1] + x0.y + bias0};
        float2 r1 = {acc[nt][2] + x1.x + bias1, acc[nt][3] + x1.y + bias1};
        *(float2*)&out[off0] = r0;
        *(float2*)&out[off1] = r1;
    }
}

// ---------------------------------------------------------------------------
extern "C" void kernel_launch(void* const* d_in, const int* in_sizes, int n_in,
                              void* d_out, int out_size)
{
    const float* x  = (const float*)d_in[0];
    const float* wt = (const float*)d_in[1];
    const float* bt = (const float*)d_in[2];
    const float* wp = (const float*)d_in[3];
    const float* bp = (const float*)d_in[4];
    const float* wg = (const float*)d_in[5];
    const float* bg = (const float*)d_in[6];
    const float* wo = (const float*)d_in[7];
    const float* bo = (const float*)d_in[8];
    float* out = (float*)d_out;

    cudaFuncSetAttribute(attn_tc, cudaFuncAttributeMaxDynamicSharedMemorySize,
                         ATTN_SMEM_BYTES);

    proj3_tc<<<dim3(NN / 64, 6, BB), 256>>>(x, wt, bt, wp, bp, wg, bg);
    pool_phi_kernel<<<(BB * MM * 32) / 256, 256>>>();
    pool_vT_kernel<<<(BB * 512 * 128) / 256, 256>>>();
    attn_tc<<<dim3(NN / 128, BB), 256, ATTN_SMEM_BYTES>>>();
    out_tc<<<dim3(NN / 64, CC / 64, BB), 256>>>(x, wo, bo, out);
}

// round 6
// speedup vs baseline: 1.0277x; 1.0277x over previous
#include <cuda_runtime.h>
#include <cuda_bf16.h>

// NonLocalAttention: B=8, C=256, Ci=128, H=W=64, N=4096, M=1024
#define BB 8
#define CC 256
#define CI 128
#define WW 64
#define NN 4096
#define MM 1024

// fp32 intermediates
__device__ float g_phif[(size_t)BB * NN * CI];
__device__ float g_gf  [(size_t)BB * NN * CI];
__device__ float g_y   [(size_t)BB * NN * CI];
// pre-split bf16 hi/lo packed intermediates
__device__ unsigned g_qH  [(size_t)BB * NN * 64];   // Q  [b][n][kpair]
__device__ unsigned g_qL  [(size_t)BB * NN * 64];
__device__ unsigned g_kH  [(size_t)BB * MM * 64];   // K  [b][m][kpair]
__device__ unsigned g_kL  [(size_t)BB * MM * 64];
__device__ unsigned g_vTH [(size_t)BB * CI * (MM/2)]; // V^T [b][ci][mpair]
__device__ unsigned g_vTL [(size_t)BB * CI * (MM/2)];

// ---------------------------------------------------------------------------
// helpers
// ---------------------------------------------------------------------------
__device__ __forceinline__ void pack2(unsigned& H, unsigned& L, float x0, float x1) {
    float h0 = __bfloat162float(__float2bfloat16_rn(x0));
    float h1 = __bfloat162float(__float2bfloat16_rn(x1));
    __nv_bfloat162 hh = __floats2bfloat162_rn(h0, h1);
    __nv_bfloat162 ll = __floats2bfloat162_rn(x0 - h0, x1 - h1);
    H = *(unsigned*)&hh;
    L = *(unsigned*)&ll;
}
__device__ __forceinline__ void mma16(float* c, unsigned a0, unsigned a1,
                                      unsigned a2, unsigned a3,
                                      unsigned b0, unsigned b1) {
    asm volatile(
        "mma.sync.aligned.m16n8k16.row.col.f32.bf16.bf16.f32 "
        "{%0,%1,%2,%3},{%4,%5,%6,%7},{%8,%9},{%0,%1,%2,%3};\n"
        : "+f"(c[0]), "+f"(c[1]), "+f"(c[2]), "+f"(c[3])
        : "r"(a0), "r"(a1), "r"(a2), "r"(a3), "r"(b0), "r"(b1));
}
__device__ __forceinline__ void ldsm4(unsigned& d0, unsigned& d1,
                                      unsigned& d2, unsigned& d3, const unsigned* p) {
    unsigned a = (unsigned)__cvta_generic_to_shared((void*)p);
    asm volatile("ldmatrix.sync.aligned.m8n8.x4.shared.b16 {%0,%1,%2,%3}, [%4];"
        : "=r"(d0), "=r"(d1), "=r"(d2), "=r"(d3) : "r"(a));
}

// ---------------------------------------------------------------------------
// Kernel 1: 3-way 1x1 conv, bf16x3 + ldmatrix, pass-major mma ordering.
// ---------------------------------------------------------------------------
__global__ __launch_bounds__(256) void proj3_tc(
    const float* __restrict__ x,
    const float* __restrict__ w_t, const float* __restrict__ b_t,
    const float* __restrict__ w_p, const float* __restrict__ b_p,
    const float* __restrict__ w_g, const float* __restrict__ b_g)
{
    __shared__ unsigned Xh[64 * 20], Xl[64 * 20];   // x  [n][kpair] pitch 20
    __shared__ unsigned Wh[64 * 20], Wl[64 * 20];   // w  [j][kpair]

    const int b  = blockIdx.z;
    const int n0 = blockIdx.x * 64;
    const int yy = blockIdx.y;

    const float* w;  const float* bias;  float* dstf = 0;  bool is_theta = false;
    if (yy < 2)      { w = w_t; bias = b_t; is_theta = true; }
    else if (yy < 4) { w = w_p; bias = b_p; dstf = g_phif; }
    else             { w = w_g; bias = b_g; dstf = g_gf;  }
    const int cib = (yy & 1) * 64;

    const int tid  = threadIdx.x;
    const int lane = tid & 31, warp = tid >> 5;
    const int gid  = lane >> 2, t4 = lane & 3;
    const int mw   = (warp >> 1) * 16, nw = (warp & 1) * 32;
    const int l16  = lane & 15, lh = lane >> 4;

    float acc[4][4] = {};
    const float* xb = x + (size_t)b * CC * NN;
    const int xn  = tid & 63;
    const int kp0 = tid >> 6;

    for (int c0 = 0; c0 < CC; c0 += 32) {
        __syncthreads();
        #pragma unroll
        for (int i = 0; i < 4; i++) {
            int kp = kp0 + i * 4;
            float v0 = xb[(size_t)(c0 + 2 * kp) * NN + n0 + xn];
            float v1 = xb[(size_t)(c0 + 2 * kp + 1) * NN + n0 + xn];
            unsigned H, L; pack2(H, L, v0, v1);
            Xh[xn * 20 + kp] = H;
            Xl[xn * 20 + kp] = L;
        }
        #pragma unroll
        for (int it = 0; it < 2; it++) {
            int j = tid + it * 256;
            int r = j >> 3, kq = j & 7;
            float4 v = *(const float4*)&w[(size_t)(cib + r) * CC + c0 + kq * 4];
            unsigned h0, l0, h1, l1;
            pack2(h0, l0, v.x, v.y);
            pack2(h1, l1, v.z, v.w);
            *(uint2*)&Wh[r * 20 + kq * 2] = make_uint2(h0, h1);
            *(uint2*)&Wl[r * 20 + kq * 2] = make_uint2(l0, l1);
        }
        __syncthreads();

        #pragma unroll
        for (int st = 0; st < 2; st++) {
            unsigned ah0, ah1, ah2, ah3, al0, al1, al2, al3;
            ldsm4(ah0, ah1, ah2, ah3, &Xh[(mw + l16) * 20 + st * 8 + lh * 4]);
            ldsm4(al0, al1, al2, al3, &Xl[(mw + l16) * 20 + st * 8 + lh * 4]);
            unsigned beh0, beh1, beh2, beh3, boh0, boh1, boh2, boh3;
            unsigned bel0, bel1, bel2, bel3, bol0, bol1, bol2, bol3;
            ldsm4(beh0, beh1, beh2, beh3, &Wh[(nw + l16) * 20 + st * 8 + lh * 4]);
            ldsm4(boh0, boh1, boh2, boh3, &Wh[(nw + 16 + l16) * 20 + st * 8 + lh * 4]);
            ldsm4(bel0, bel1, bel2, bel3, &Wl[(nw + l16) * 20 + st * 8 + lh * 4]);
            ldsm4(bol0, bol1, bol2, bol3, &Wl[(nw + 16 + l16) * 20 + st * 8 + lh * 4]);
            // pass hh (4 independent accums)
            mma16(acc[0], ah0, ah1, ah2, ah3, beh0, beh2);
            mma16(acc[1], ah0, ah1, ah2, ah3, beh1, beh3);
            mma16(acc[2], ah0, ah1, ah2, ah3, boh0, boh2);
            mma16(acc[3], ah0, ah1, ah2, ah3, boh1, boh3);
            // pass hl
            mma16(acc[0], ah0, ah1, ah2, ah3, bel0, bel2);
            mma16(acc[1], ah0, ah1, ah2, ah3, bel1, bel3);
            mma16(acc[2], ah0, ah1, ah2, ah3, bol0, bol2);
            mma16(acc[3], ah0, ah1, ah2, ah3, bol1, bol3);
            // pass lh
            mma16(acc[0], al0, al1, al2, al3, beh0, beh2);
            mma16(acc[1], al0, al1, al2, al3, beh1, beh3);
            mma16(acc[2], al0, al1, al2, al3, boh0, boh2);
            mma16(acc[3], al0, al1, al2, al3, boh1, boh3);
        }
    }

    const size_t base = (size_t)b * NN + n0;
    #pragma unroll
    for (int nt = 0; nt < 4; nt++) {
        int col = cib + nw + nt * 8 + 2 * t4;
        float bb0 = bias[col], bb1 = bias[col + 1];
        int r0 = mw + gid;
        float2 v0 = {acc[nt][0] + bb0, acc[nt][1] + bb1};
        float2 v1 = {acc[nt][2] + bb0, acc[nt][3] + bb1};
        if (is_theta) {
            int kw = col >> 1;
            unsigned H, L;
            pack2(H, L, v0.x, v0.y);
            g_qH[(base + r0) * 64 + kw] = H;
            g_qL[(base + r0) * 64 + kw] = L;
            pack2(H, L, v1.x, v1.y);
            g_qH[(base + r0 + 8) * 64 + kw] = H;
            g_qL[(base + r0 + 8) * 64 + kw] = L;
        } else {
            *(float2*)&dstf[(base + r0) * CI + col]     = v0;
            *(float2*)&dstf[(base + r0 + 8) * CI + col] = v1;
        }
    }
}

// ---------------------------------------------------------------------------
// Kernel 2a: pool phi -> packed bf16 hi/lo [b][m][kpair]
// ---------------------------------------------------------------------------
__global__ __launch_bounds__(256) void pool_phi_kernel()
{
    int idx = blockIdx.x * 256 + threadIdx.x;     // BB*MM*32
    int c4 = (idx & 31) * 4;
    int m  = (idx >> 5) & (MM - 1);
    int b  = idx >> 15;
    int hp = m >> 5, wp = m & 31;
    int n00 = (hp * 2) * WW + wp * 2;
    size_t base = ((size_t)b * NN + n00) * CI + c4;

    float4 a0 = *(const float4*)&g_phif[base];
    float4 a1 = *(const float4*)&g_phif[base + CI];
    float4 a2 = *(const float4*)&g_phif[base + (size_t)WW * CI];
    float4 a3 = *(const float4*)&g_phif[base + (size_t)WW * CI + CI];
    float4 r;
    r.x = fmaxf(fmaxf(a0.x, a1.x), fmaxf(a2.x, a3.x));
    r.y = fmaxf(fmaxf(a0.y, a1.y), fmaxf(a2.y, a3.y));
    r.z = fmaxf(fmaxf(a0.z, a1.z), fmaxf(a2.z, a3.z));
    r.w = fmaxf(fmaxf(a0.w, a1.w), fmaxf(a2.w, a3.w));

    unsigned h0, l0, h1, l1;
    pack2(h0, l0, r.x, r.y);
    pack2(h1, l1, r.z, r.w);
    size_t dst = ((size_t)b * MM + m) * 64 + (c4 >> 1);
    *(uint2*)&g_kH[dst] = make_uint2(h0, h1);
    *(uint2*)&g_kL[dst] = make_uint2(l0, l1);
}

// ---------------------------------------------------------------------------
// Kernel 2b: pool g + transpose -> V^T packed along m-pairs [b][ci][mpair]
// ---------------------------------------------------------------------------
__global__ __launch_bounds__(256) void pool_vT_kernel()
{
    int idx = blockIdx.x * 256 + threadIdx.x;     // BB * 512 * 128
    int ci = idx & 127;
    int mp = (idx >> 7) & 511;
    int b  = idx >> 16;

    float v[2];
    #pragma unroll
    for (int j = 0; j < 2; j++) {
        int m = 2 * mp + j;
        int hp = m >> 5, wp = m & 31;
        int n00 = (hp * 2) * WW + wp * 2;
        size_t base = ((size_t)b * NN + n00) * CI + ci;
        float a0 = g_gf[base];
        float a1 = g_gf[base + CI];
        float a2 = g_gf[base + (size_t)WW * CI];
        float a3 = g_gf[base + (size_t)WW * CI + CI];
        v[j] = fmaxf(fmaxf(a0, a1), fmaxf(a2, a3));
    }
    unsigned H, L; pack2(H, L, v[0], v[1]);
    size_t dst = ((size_t)b * CI + ci) * (MM / 2) + mp;
    g_vTH[dst] = H;
    g_vTL[dst] = L;
}

// ---------------------------------------------------------------------------
// Kernel 3: flash attention, pass-major mma ordering for ILP.
// ---------------------------------------------------------------------------
#define ATTN_WORDS (2*128*68 + 2*64*68 + 2*128*36)
#define ATTN_SMEM_BYTES (ATTN_WORDS * 4)

__global__ __launch_bounds__(256, 1) void attn_tc()
{
    extern __shared__ unsigned smu[];
    unsigned* QhW = smu;                 // [q=128][kw] pitch 68
    unsigned* QlW = QhW + 128 * 68;
    unsigned* KhW = QlW + 128 * 68;      // [m=64][kw] pitch 68
    unsigned* KlW = KhW + 64 * 68;
    unsigned* VtH = KlW + 64 * 68;       // [ci=128][mp] pitch 36
    unsigned* VtL = VtH + 128 * 36;

    const int b  = blockIdx.y;
    const int n0 = blockIdx.x * 128;
    const int tid  = threadIdx.x;
    const int lane = tid & 31, warp = tid >> 5;
    const int gid  = lane >> 2, t4 = lane & 3;
    const int qw   = warp * 16;
    const int l16  = lane & 15, lh = lane >> 4;

    // stage Q: straight packed copies
    const unsigned* QgH = g_qH + ((size_t)b * NN + n0) * 64;
    const unsigned* QgL = g_qL + ((size_t)b * NN + n0) * 64;
    #pragma unroll
    for (int it = 0; it < 8; it++) {
        int j = tid + it * 256;
        int q = j >> 4, sg = (j & 15) * 4;
        *(uint4*)&QhW[q * 68 + sg] = *(const uint4*)&QgH[q * 64 + sg];
        *(uint4*)&QlW[q * 68 + sg] = *(const uint4*)&QgL[q * 64 + sg];
    }

    float o[16][4];
    #pragma unroll
    for (int i = 0; i < 16; i++)
        #pragma unroll
        for (int jj = 0; jj < 4; jj++) o[i][jj] = 0.f;
    float m_lo = -1e30f, m_hi = -1e30f, l_lo = 0.f, l_hi = 0.f;

    for (int m0 = 0; m0 < MM; m0 += 64) {
        __syncthreads();
        const unsigned* KgH = g_kH + ((size_t)b * MM + m0) * 64;
        const unsigned* KgL = g_kL + ((size_t)b * MM + m0) * 64;
        const unsigned* VgH = g_vTH + (size_t)b * CI * (MM/2) + (m0 >> 1);
        const unsigned* VgL = g_vTL + (size_t)b * CI * (MM/2) + (m0 >> 1);
        #pragma unroll
        for (int it = 0; it < 4; it++) {
            int j = tid + it * 256;
            int m = j >> 4, sg = (j & 15) * 4;
            *(uint4*)&KhW[m * 68 + sg] = *(const uint4*)&KgH[m * 64 + sg];
            *(uint4*)&KlW[m * 68 + sg] = *(const uint4*)&KgL[m * 64 + sg];
            int ci = j >> 3, sv = (j & 7) * 4;
            *(uint4*)&VtH[ci * 36 + sv] = *(const uint4*)&VgH[(size_t)ci * (MM/2) + sv];
            *(uint4*)&VtL[ci * 36 + sv] = *(const uint4*)&VgL[(size_t)ci * (MM/2) + sv];
        }
        __syncthreads();

        // S = Q K^T : bf16x3, pass-major over ntp-pairs (dep distance 4)
        float s[8][4];
        #pragma unroll
        for (int nt = 0; nt < 8; nt++)
            #pragma unroll
            for (int jj = 0; jj < 4; jj++) s[nt][jj] = 0.f;

        #pragma unroll
        for (int ks = 0; ks < 8; ks++) {
            unsigned ah0, ah1, ah2, ah3, al0, al1, al2, al3;
            ldsm4(ah0, ah1, ah2, ah3, &QhW[(qw + l16) * 68 + ks * 8 + lh * 4]);
            ldsm4(al0, al1, al2, al3, &QlW[(qw + l16) * 68 + ks * 8 + lh * 4]);
            #pragma unroll
            for (int pp = 0; pp < 2; pp++) {
                unsigned beh0, beh1, beh2, beh3, boh0, boh1, boh2, boh3;
                unsigned bel0, bel1, bel2, bel3, bol0, bol1, bol2, bol3;
                ldsm4(beh0, beh1, beh2, beh3, &KhW[((2*pp)   * 16 + l16) * 68 + ks * 8 + lh * 4]);
                ldsm4(boh0, boh1, boh2, boh3, &KhW[((2*pp+1) * 16 + l16) * 68 + ks * 8 + lh * 4]);
                ldsm4(bel0, bel1, bel2, bel3, &KlW[((2*pp)   * 16 + l16) * 68 + ks * 8 + lh * 4]);
                ldsm4(bol0, bol1, bol2, bol3, &KlW[((2*pp+1) * 16 + l16) * 68 + ks * 8 + lh * 4]);
                float* s0 = s[4*pp+0]; float* s1 = s[4*pp+1];
                float* s2 = s[4*pp+2]; float* s3 = s[4*pp+3];
                // hh
                mma16(s0, ah0, ah1, ah2, ah3, beh0, beh2);
                mma16(s1, ah0, ah1, ah2, ah3, beh1, beh3);
                mma16(s2, ah0, ah1, ah2, ah3, boh0, boh2);
                mma16(s3, ah0, ah1, ah2, ah3, boh1, boh3);
                // hl
                mma16(s0, ah0, ah1, ah2, ah3, bel0, bel2);
                mma16(s1, ah0, ah1, ah2, ah3, bel1, bel3);
                mma16(s2, ah0, ah1, ah2, ah3, bol0, bol2);
                mma16(s3, ah0, ah1, ah2, ah3, bol1, bol3);
                // lh
                mma16(s0, al0, al1, al2, al3, beh0, beh2);
                mma16(s1, al0, al1, al2, al3, beh1, beh3);
                mma16(s2, al0, al1, al2, al3, boh0, boh2);
                mma16(s3, al0, al1, al2, al3, boh1, boh3);
            }
        }

        // online softmax; p stays in registers
        float mx0 = -1e30f, mx1 = -1e30f;
        #pragma unroll
        for (int nt = 0; nt < 8; nt++) {
            mx0 = fmaxf(mx0, fmaxf(s[nt][0], s[nt][1]));
            mx1 = fmaxf(mx1, fmaxf(s[nt][2], s[nt][3]));
        }
        mx0 = fmaxf(mx0, __shfl_xor_sync(0xffffffffu, mx0, 1));
        mx0 = fmaxf(mx0, __shfl_xor_sync(0xffffffffu, mx0, 2));
        mx1 = fmaxf(mx1, __shfl_xor_sync(0xffffffffu, mx1, 1));
        mx1 = fmaxf(mx1, __shfl_xor_sync(0xffffffffu, mx1, 2));
        float mn0 = fmaxf(m_lo, mx0), mn1 = fmaxf(m_hi, mx1);
        float al0 = __expf(m_lo - mn0), al1 = __expf(m_hi - mn1);
        float s0v = 0.f, s1v = 0.f;
        #pragma unroll
        for (int nt = 0; nt < 8; nt++) {
            s[nt][0] = __expf(s[nt][0] - mn0);
            s[nt][1] = __expf(s[nt][1] - mn0);
            s[nt][2] = __expf(s[nt][2] - mn1);
            s[nt][3] = __expf(s[nt][3] - mn1);
            s0v += s[nt][0] + s[nt][1];
            s1v += s[nt][2] + s[nt][3];
        }
        s0v += __shfl_xor_sync(0xffffffffu, s0v, 1);
        s0v += __shfl_xor_sync(0xffffffffu, s0v, 2);
        s1v += __shfl_xor_sync(0xffffffffu, s1v, 1);
        s1v += __shfl_xor_sync(0xffffffffu, s1v, 2);
        l_lo = l_lo * al0 + s0v; m_lo = mn0;
        l_hi = l_hi * al1 + s1v; m_hi = mn1;
        #pragma unroll
        for (int nt = 0; nt < 16; nt++) {
            o[nt][0] *= al0; o[nt][1] *= al0;
            o[nt][2] *= al1; o[nt][3] *= al1;
        }

        // O += P V : bf16x3, pass-major over ntp-pairs (dep distance 4)
        #pragma unroll
        for (int ks2 = 0; ks2 < 4; ks2++) {
            unsigned paH[4], paL[4];
            pack2(paH[0], paL[0], s[2*ks2][0],   s[2*ks2][1]);
            pack2(paH[1], paL[1], s[2*ks2][2],   s[2*ks2][3]);
            pack2(paH[2], paL[2], s[2*ks2+1][0], s[2*ks2+1][1]);
            pack2(paH[3], paL[3], s[2*ks2+1][2], s[2*ks2+1][3]);
            #pragma unroll
            for (int pp = 0; pp < 4; pp++) {
                unsigned veh0, veh1, veh2, veh3, voh0, voh1, voh2, voh3;
                unsigned vel0, vel1, vel2, vel3, vol0, vol1, vol2, vol3;
                ldsm4(veh0, veh1, veh2, veh3, &VtH[((2*pp)   * 16 + l16) * 36 + ks2 * 8 + lh * 4]);
                ldsm4(voh0, voh1, voh2, voh3, &VtH[((2*pp+1) * 16 + l16) * 36 + ks2 * 8 + lh * 4]);
                ldsm4(vel0, vel1, vel2, vel3, &VtL[((2*pp)   * 16 + l16) * 36 + ks2 * 8 + lh * 4]);
                ldsm4(vol0, vol1, vol2, vol3, &VtL[((2*pp+1) * 16 + l16) * 36 + ks2 * 8 + lh * 4]);
                float* o0 = o[4*pp+0]; float* o1 = o[4*pp+1];
                float* o2 = o[4*pp+2]; float* o3 = o[4*pp+3];
                // Ph Vh
                mma16(o0, paH[0], paH[1], paH[2], paH[3], veh0, veh2);
                mma16(o1, paH[0], paH[1], paH[2], paH[3], veh1, veh3);
                mma16(o2, paH[0], paH[1], paH[2], paH[3], voh0, voh2);
                mma16(o3, paH[0], paH[1], paH[2], paH[3], voh1, voh3);
                // Ph Vl
                mma16(o0, paH[0], paH[1], paH[2], paH[3], vel0, vel2);
                mma16(o1, paH[0], paH[1], paH[2], paH[3], vel1, vel3);
                mma16(o2, paH[0], paH[1], paH[2], paH[3], vol0, vol2);
                mma16(o3, paH[0], paH[1], paH[2], paH[3], vol1, vol3);
                // Pl Vh
                mma16(o0, paL[0], paL[1], paL[2], paL[3], veh0, veh2);
                mma16(o1, paL[0], paL[1], paL[2], paL[3], veh1, veh3);
                mma16(o2, paL[0], paL[1], paL[2], paL[3], voh0, voh2);
                mma16(o3, paL[0], paL[1], paL[2], paL[3], voh1, voh3);
            }
        }
    }

    float i0 = 1.f / l_lo, i1 = 1.f / l_hi;
    float* yb = g_y + ((size_t)b * NN + n0) * CI;
    #pragma unroll
    for (int nt = 0; nt < 16; nt++) {
        int cc = nt * 8 + 2 * t4;
        float2 w0 = {o[nt][0] * i0, o[nt][1] * i0};
        float2 w1 = {o[nt][2] * i1, o[nt][3] * i1};
        *(float2*)&yb[(size_t)(qw + gid) * CI + cc]     = w0;
        *(float2*)&yb[(size_t)(qw + gid + 8) * CI + cc] = w1;
    }
}

// ---------------------------------------------------------------------------
// Kernel 4: out conv + bias + residual, bf16x3 + ldmatrix, pass-major.
// ---------------------------------------------------------------------------
__global__ __launch_bounds__(256) void out_tc(
    const float* __restrict__ x,
    const float* __restrict__ wo, const float* __restrict__ bo,
    float* __restrict__ out)
{
    __shared__ unsigned Ah[64 * 20], Al[64 * 20];   // wo [c][kpair]
    __shared__ unsigned Bh[64 * 20], Bl[64 * 20];   // y  [n][kpair]

    const int b  = blockIdx.z;
    const int c0 = blockIdx.y * 64;
    const int n0 = blockIdx.x * 64;
    const int tid  = threadIdx.x;
    const int lane = tid & 31, warp = tid >> 5;
    const int gid  = lane >> 2, t4 = lane & 3;
    const int mw   = (warp >> 1) * 16, nw = (warp & 1) * 32;
    const int l16  = lane & 15, lh = lane >> 4;

    const float* yb = g_y + ((size_t)b * NN + n0) * CI;
    float acc[4][4] = {};

    for (int k0 = 0; k0 < CI; k0 += 32) {
        __syncthreads();
        #pragma unroll
        for (int it = 0; it < 2; it++) {
            int j = tid + it * 256;
            int r = j >> 3, kq = j & 7;
            float4 a = *(const float4*)&wo[(size_t)(c0 + r) * CI + k0 + kq * 4];
            unsigned h0, l0, h1, l1;
            pack2(h0, l0, a.x, a.y);
            pack2(h1, l1, a.z, a.w);
            *(uint2*)&Ah[r * 20 + kq * 2] = make_uint2(h0, h1);
            *(uint2*)&Al[r * 20 + kq * 2] = make_uint2(l0, l1);
            float4 yv = *(const float4*)&yb[(size_t)r * CI + k0 + kq * 4];
            pack2(h0, l0, yv.x, yv.y);
            pack2(h1, l1, yv.z, yv.w);
            *(uint2*)&Bh[r * 20 + kq * 2] = make_uint2(h0, h1);
            *(uint2*)&Bl[r * 20 + kq * 2] = make_uint2(l0, l1);
        }
        __syncthreads();

        #pragma unroll
        for (int st = 0; st < 2; st++) {
            unsigned ah0, ah1, ah2, ah3, al0, al1, al2, al3;
            ldsm4(ah0, ah1, ah2, ah3, &Ah[(mw + l16) * 20 + st * 8 + lh * 4]);
            ldsm4(al0, al1, al2, al3, &Al[(mw + l16) * 20 + st * 8 + lh * 4]);
            unsigned beh0, beh1, beh2, beh3, boh0, boh1, boh2, boh3;
            unsigned bel0, bel1, bel2, bel3, bol0, bol1, bol2, bol3;
            ldsm4(beh0, beh1, beh2, beh3, &Bh[(nw + l16) * 20 + st * 8 + lh * 4]);
            ldsm4(boh0, boh1, boh2, boh3, &Bh[(nw + 16 + l16) * 20 + st * 8 + lh * 4]);
            ldsm4(bel0, bel1, bel2, bel3, &Bl[(nw + l16) * 20 + st * 8 + lh * 4]);
            ldsm4(bol0, bol1, bol2, bol3, &Bl[(nw + 16 + l16) * 20 + st * 8 + lh * 4]);
            // hh
            mma16(acc[0], ah0, ah1, ah2, ah3, beh0, beh2);
            mma16(acc[1], ah0, ah1, ah2, ah3, beh1, beh3);
            mma16(acc[2], ah0, ah1, ah2, ah3, boh0, boh2);
            mma16(acc[3], ah0, ah1, ah2, ah3, boh1, boh3);
            // hl
            mma16(acc[0], ah0, ah1, ah2, ah3, bel0, bel2);
            mma16(acc[1], ah0, ah1, ah2, ah3, bel1, bel3);
            mma16(acc[2], ah0, ah1, ah2, ah3, bol0, bol2);
            mma16(acc[3], ah0, ah1, ah2, ah3, bol1, bol3);
            // lh
            mma16(acc[0], al0, al1, al2, al3, beh0, beh2);
            mma16(acc[1], al0, al1, al2, al3, beh1, beh3);
            mma16(acc[2], al0, al1, al2, al3, boh0, boh2);
            mma16(acc[3], al0, al1, al2, al3, boh1, boh3);
        }
    }

    #pragma unroll
    for (int nt = 0; nt < 4; nt++) {
        int c = c0 + mw + gid;
        int n = n0 + nw + nt * 8 + 2 * t4;
        float bias0 = bo[c], bias1 = bo[c + 8];
        size_t off0 = ((size_t)b * CC + c) * NN + n;
        size_t off1 = ((size_t)b * CC + c + 8) * NN + n;
        float2 x0 = *(const float2*)&x[off0];
        float2 x1 = *(const float2*)&x[off1];
        float2 r0 = {acc[nt][0] + x0.x + bias0, acc[nt][1] + x0.y + bias0};
        float2 r1 = {acc[nt][2] + x1.x + bias1, acc[nt][3] + x1.y + bias1};
        *(float2*)&out[off0] = r0;
        *(float2*)&out[off1] = r1;
    }
}

// ---------------------------------------------------------------------------
extern "C" void kernel_launch(void* const* d_in, const int* in_sizes, int n_in,
                              void* d_out, int out_size)
{
    const float* x  = (const float*)d_in[0];
    const float* wt = (const float*)d_in[1];
    const float* bt = (const float*)d_in[2];
    const float* wp = (const float*)d_in[3];
    const float* bp = (const float*)d_in[4];
    const float* wg = (const float*)d_in[5];
    const float* bg = (const float*)d_in[6];
    const float* wo = (const float*)d_in[7];
    const float* bo = (const float*)d_in[8];
    float* out = (float*)d_out;

    cudaFuncSetAttribute(attn_tc, cudaFuncAttributeMaxDynamicSharedMemorySize,
                         ATTN_SMEM_BYTES);

    proj3_tc<<<dim3(NN / 64, 6, BB), 256>>>(x, wt, bt, wp, bp, wg, bg);
    pool_phi_kernel<<<(BB * MM * 32) / 256, 256>>>();
    pool_vT_kernel<<<(BB * 512 * 128) / 256, 256>>>();
    attn_tc<<<dim3(NN / 128, BB), 256, ATTN_SMEM_BYTES>>>();
    out_tc<<<dim3(NN / 64, CC / 64, BB), 256>>>(x, wo, bo, out);
}